// round 17
// baseline (speedup 1.0000x reference)
#include <cuda_runtime.h>
#include <stdint.h>

// GraphRewiring: transitive closure of body-edge adjacency (attr==0),
// emit shortcut edges (closure & ~adj) appended to original edge list.
//
// R17 = R16 (4-launch split) with K4 at 2 WARPS PER ROW:
//   2048 warps (128x512), warp pair (row, half); both warps compute the
//   row's closure redundantly (cheap, mostly analytic; twin-warp adj loads
//   share L2 lines), each emits half the row (12 STG.128 instead of 24).
//   Halves the per-warp serial latency chain and doubles warps/SM to 16.
//
//   K1 init : zero adj/radj, pivot=-1; detect int64-vs-int32   (128x256)
//   K2 build: scatter adj/radj bitsets, pivot=max body dst,
//             copy original edges to output head (1 edge/thread)
//   K3 bfs  : 2 blocks x 1024 (block0 fwd, block1 bwd), 32 warps,
//             1 frontier word per warp -> F, B
//   K4 close: 2 warps/row closed-form closure + coalesced half-row emit
//
// Closed-form closure (validated R11/R12):
//   closure(row) = adjrow u U_{k in adjrow} closure(k), absorbed by:
//     (a) k in F&B => closure(k) = F        (zero loads; p in F)
//     (b) k in B   => closure(k) >= F u {p} (one ballot, analytic)
//     (c) F already in acc => any k in F absorbed (closure(k) <= F)
//
// Output layout (float32, out_size = 3*(E+N*N)):
//   [0, E)               : edge_index[0] (src) as float
//   [E, E+NN)            : new_src
//   [E+NN, 2E+NN)        : edge_index[1] (dst) as float
//   [2E+NN, 2E+2NN)      : new_dst
//   [2(E+NN), 2(E+NN)+E) : edge_attr copy
//   [2(E+NN)+E, 3(E+NN)) : new_attr (3.0 if shortcut else -1.0)

#define N_NODES 1024
#define NW 32
#define FULLMASK 0xFFFFFFFFu

static __device__ uint32_t g_adj[N_NODES * NW];
static __device__ uint32_t g_radj[N_NODES * NW];
static __device__ uint32_t g_F[NW];
static __device__ uint32_t g_B[NW];
static __device__ int g_pivot;
static __device__ int g_i64flag;

// ---------------------------------------------------------------------------
// K1: zero scratch, detect dtype. 128 blocks x 256 threads.
__global__ void init_kernel(const int* __restrict__ ei32) {
    int t = blockIdx.x * blockDim.x + threadIdx.x;   // 0..32767
    g_adj[t] = 0u;
    g_radj[t] = 0u;
    if (t == 0) {
        g_pivot = -1;
        // int64 little-endian with node ids < 1024 => every odd word is 0.
        int allzero = 1;
        for (int k = 0; k < 64; k++)
            if (ei32[2 * k + 1] != 0) { allzero = 0; break; }
        g_i64flag = allzero;
    }
}

// ---------------------------------------------------------------------------
// K2: scatter adj/radj + pivot + copy originals. One edge per thread.
__global__ void build_kernel(const int* __restrict__ ei32,
                             const float* __restrict__ attr,
                             float* __restrict__ out, int E) {
    __shared__ int sPivMax;
    const int NN = N_NODES * N_NODES;
    if (threadIdx.x == 0) sPivMax = -1;
    __syncthreads();

    int e = blockIdx.x * blockDim.x + threadIdx.x;
    int lane = threadIdx.x & 31;
    bool v = (e < E);
    int src = 0, dst = 0; float a = 1.0f;
    if (v) {
        if (g_i64flag) { src = ei32[2 * e]; dst = ei32[2 * (E + e)]; }
        else           { src = ei32[e];     dst = ei32[E + e]; }
        a = attr[e];
        out[e] = (float)src;
        out[(E + NN) + e] = (float)dst;
        out[2 * (E + NN) + e] = a;
    }
    bool body = v && (a == 0.0f);
    if (body) {
        atomicOr(&g_adj[src * NW + (dst >> 5)], 1u << (dst & 31));
        atomicOr(&g_radj[dst * NW + (src >> 5)], 1u << (src & 31));
    }
    int m = __reduce_max_sync(FULLMASK, body ? dst : -1);
    if (lane == 0 && m >= 0) atomicMax(&sPivMax, m);
    __syncthreads();
    if (threadIdx.x == 0 && sPivMax >= 0) atomicMax(&g_pivot, sPivMax);
}

// ---------------------------------------------------------------------------
// K3: single-source BFS to fixpoint. block 0: forward -> g_F;
//     block 1: backward -> g_B. 32 warps, 1 frontier word per warp.
__global__ void __launch_bounds__(1024) bfs_kernel() {
    __shared__ uint32_t sR[NW];
    const int lane = threadIdx.x & 31;
    const int wid  = threadIdx.x >> 5;               // 0..31

    const uint32_t* Adj = (blockIdx.x == 0) ? g_adj : g_radj;
    const int p = g_pivot;
    if (lane == 0) sR[wid] = (p >= 0) ? Adj[p * NW + wid] : 0u;
    __syncthreads();

    if (p >= 0) {
        uint32_t expanded = 0;                       // own word, in register
        #pragma unroll 1
        for (int level = 0; level < N_NODES + 1; level++) {
            uint32_t cur = sR[wid];                  // post-sync, merged
            uint32_t fr = cur & ~expanded;           // warp-uniform
            expanded = cur;
            if (!__syncthreads_or(fr != 0u)) break;

            uint32_t accum = 0;                      // lane l = word l
            const uint32_t* pk = &Adj[(wid << 10) + lane];
            uint32_t bits = fr;
            while (bits) {
                int j0 = __ffs(bits) - 1; bits &= bits - 1;
                int j1 = j0, j2 = j0, j3 = j0;
                int j4 = j0, j5 = j0, j6 = j0, j7 = j0;
                if (bits) { j1 = __ffs(bits) - 1; bits &= bits - 1; }
                if (bits) { j2 = __ffs(bits) - 1; bits &= bits - 1; }
                if (bits) { j3 = __ffs(bits) - 1; bits &= bits - 1; }
                if (bits) { j4 = __ffs(bits) - 1; bits &= bits - 1; }
                if (bits) { j5 = __ffs(bits) - 1; bits &= bits - 1; }
                if (bits) { j6 = __ffs(bits) - 1; bits &= bits - 1; }
                if (bits) { j7 = __ffs(bits) - 1; bits &= bits - 1; }
                uint32_t v0 = pk[j0 << 5];
                uint32_t v1 = pk[j1 << 5];
                uint32_t v2 = pk[j2 << 5];
                uint32_t v3 = pk[j3 << 5];
                uint32_t v4 = pk[j4 << 5];
                uint32_t v5 = pk[j5 << 5];
                uint32_t v6 = pk[j6 << 5];
                uint32_t v7 = pk[j7 << 5];
                accum |= (v0 | v1) | (v2 | v3) | (v4 | v5) | (v6 | v7);
            }
            if (accum) atomicOr(&sR[lane], accum);
            __syncthreads();
        }
    }
    if (threadIdx.x < NW) {
        if (blockIdx.x == 0) g_F[threadIdx.x] = sR[threadIdx.x];
        else                 g_B[threadIdx.x] = sR[threadIdx.x];
    }
}

// ---------------------------------------------------------------------------
// K4: 2 warps per row. Both compute the closure (redundant, cheap); each
// emits half the row. 128 blocks x 512 threads = 2048 warps.
__global__ void __launch_bounds__(512)
closure_emit_kernel(float* __restrict__ out, int E) {
    __shared__ uint32_t sF[NW], sB[NW];
    __shared__ int sPiv;

    const int tid  = blockIdx.x * 512 + threadIdx.x;
    const int lane = threadIdx.x & 31;
    const int warp = tid >> 5;                       // 0..2047
    const int row  = warp >> 1;                      // 0..1023
    const int half = warp & 1;                       // 0 or 1
    const int NN   = N_NODES * N_NODES;

    if (threadIdx.x < NW)            sF[threadIdx.x] = g_F[threadIdx.x];
    else if (threadIdx.x < 2 * NW)   sB[threadIdx.x - NW] = g_B[threadIdx.x - NW];
    else if (threadIdx.x == 2 * NW)  sPiv = g_pivot;
    __syncthreads();

    const uint32_t Fl  = sF[lane];                   // conflict-free broadcast
    const uint32_t Bl  = sB[lane];
    const uint32_t FBl = Fl & Bl;
    const int p = sPiv;
    const uint32_t pbit = (p >= 0 && lane == (p >> 5)) ? (1u << (p & 31)) : 0u;

    const uint32_t adjrow = g_adj[(row << 5) + lane];
    const int inB = (__shfl_sync(FULLMASK, Bl, row >> 5) >> (row & 31)) & 1;

    uint32_t acc = adjrow;
    bool haveF = false;
    if (inB) { acc |= Fl | pbit; haveF = true; }     // closure(row) >= F u {p}
    uint32_t expanded = 0;

    #pragma unroll 1
    for (int round = 0; round < N_NODES; round++) {
        uint32_t delta = acc & ~expanded;
        if (!__any_sync(FULLMASK, delta != 0u)) break;
        expanded = acc;
        uint32_t add = 0;

        bool hitB = __any_sync(FULLMASK, (delta & Bl) != 0u);
        bool willF = haveF || hitB;
        if (hitB) add |= Fl | pbit;

        uint32_t loadbits = delta & ~FBl;            // F&B: closure=F, no load
        if (willF) loadbits &= ~Fl;                  // F absorbed once in acc

        uint32_t wordmask = __ballot_sync(FULLMASK, loadbits != 0u);
        while (wordmask) {
            int l = __ffs(wordmask) - 1; wordmask &= wordmask - 1;
            uint32_t bits = __shfl_sync(FULLMASK, loadbits, l);
            const uint32_t* pk = &g_adj[(l << 10) + lane];
            while (bits) {
                int j0 = __ffs(bits) - 1; bits &= bits - 1;
                int j1 = j0, j2 = j0, j3 = j0;
                if (bits) { j1 = __ffs(bits) - 1; bits &= bits - 1; }
                if (bits) { j2 = __ffs(bits) - 1; bits &= bits - 1; }
                if (bits) { j3 = __ffs(bits) - 1; bits &= bits - 1; }
                add |= pk[j0 << 5] | pk[j1 << 5] | pk[j2 << 5] | pk[j3 << 5];
            }
        }

        uint32_t na = acc | add;
        haveF = willF;
        if (__all_sync(FULLMASK, na == acc)) break;
        acc = na;
    }

    // Emit this warp's HALF of the row (512 contiguous floats per segment).
    uint32_t sc = acc & ~adjrow;
    const float fi = (float)row;
    float* so = out + E + (row << 10);                    // new_src row
    float* dd = out + (E + NN) + E + (row << 10);         // new_dst row
    float* ao = out + 2 * (E + NN) + E + (row << 10);     // new_attr row

    if ((E & 3) == 0) {
        // Coalesced: 4 iterations x 3 float4 stores per warp; lane l covers
        // floats f = it*128 + l*4 + {0..3}; word = it*4+(l>>3); nib = (l&7)*4.
        #pragma unroll
        for (int q = 0; q < 4; q++) {
            int it = (half << 2) + q;                // 0..7 across the pair
            int w = (it << 2) + (lane >> 3);
            uint32_t nib = (__shfl_sync(FULLMASK, sc, w) >> ((lane & 7) << 2)) & 0xFu;
            int f = (it << 7) + (lane << 2);
            bool b0 = nib & 1u, b1 = (nib >> 1) & 1u;
            bool b2 = (nib >> 2) & 1u, b3 = (nib >> 3) & 1u;
            float4 s4 = make_float4(b0 ? fi : 0.f, b1 ? fi : 0.f,
                                    b2 ? fi : 0.f, b3 ? fi : 0.f);
            float4 d4 = make_float4(b0 ? (float)(f + 0) : 0.f,
                                    b1 ? (float)(f + 1) : 0.f,
                                    b2 ? (float)(f + 2) : 0.f,
                                    b3 ? (float)(f + 3) : 0.f);
            float4 a4 = make_float4(b0 ? 3.f : -1.f, b1 ? 3.f : -1.f,
                                    b2 ? 3.f : -1.f, b3 ? 3.f : -1.f);
            *(float4*)(so + f) = s4;
            *(float4*)(dd + f) = d4;
            *(float4*)(ao + f) = a4;
        }
    } else {
        // Scalar fallback (unaligned E). Still coalesced per instruction.
        #pragma unroll 1
        for (int q = 0; q < 16; q++) {
            int f = ((half << 4) + q) * 32 + lane;   // float index in row
            uint32_t scw = __shfl_sync(FULLMASK, sc, f >> 5);
            bool b = (scw >> (f & 31)) & 1u;
            so[f] = b ? fi : 0.f;
            dd[f] = b ? (float)f : 0.f;
            ao[f] = b ? 3.f : -1.f;
        }
    }
}

// ---------------------------------------------------------------------------
extern "C" void kernel_launch(void* const* d_in, const int* in_sizes, int n_in,
                              void* d_out, int out_size) {
    const int* ei = (const int*)d_in[0];
    const float* attr = (const float*)d_in[1];
    float* out = (float*)d_out;
    int E = in_sizes[1];

    init_kernel<<<128, 256>>>(ei);
    build_kernel<<<(E + 255) / 256, 256>>>(ei, attr, out, E);
    bfs_kernel<<<2, 1024>>>();
    closure_emit_kernel<<<128, 512>>>(out, E);
}